// round 1
// baseline (speedup 1.0000x reference)
#include <cuda_runtime.h>
#include <cstdint>

// ---------------- problem dims ----------------
#define T_DIM 256      // temporal crop
#define HW    128      // spatial H == W
#define HW2   (HW*HW)  // 16384
#define KW    129      // half-spectrum bins along W (Hermitian)
#define KWS   132      // padded stride for kw (32B-aligned rows of float2)
#define BD    2        // b*d

// ---------------- device scratch (no allocation allowed) ----------------
__device__ static float  d_tmp [(size_t)BD*T_DIM*HW*HW];          // 33.5 MB (real; also holds vol)
__device__ static float2 d_bufA[(size_t)BD*T_DIM*HW*KWS];         // 69.2 MB (after W-FFT / before W-IFFT)
__device__ static float2 d_bufB[(size_t)BD*T_DIM*T_DIM*KWS];      // 138 MB  (after H-FFT; T pass in-place)
__device__ static float2 d_W512[256];                              // twiddles exp(-2*pi*i*k/512)
__device__ static int    d_cols[2][256][256];
__device__ static float  d_vals[2][256][256];
__device__ static int    d_cnt [2][256];

// ---------------- complex helpers ----------------
static __device__ __forceinline__ float2 cadd(float2 a, float2 b){ return make_float2(a.x+b.x, a.y+b.y); }
static __device__ __forceinline__ float2 csub(float2 a, float2 b){ return make_float2(a.x-b.x, a.y-b.y); }
static __device__ __forceinline__ float2 cmul(float2 a, float2 b){ return make_float2(a.x*b.x - a.y*b.y, a.x*b.y + a.y*b.x); }

static __device__ __forceinline__ int brev8(int i){ return __brev((unsigned)i) >> 24; }
static __device__ __forceinline__ int brev9(int i){ return __brev((unsigned)i) >> 23; }

// ---------------- init: twiddle table + CSR of mtx/mtxi ----------------
__global__ void k_init(const float* __restrict__ mtx, const float* __restrict__ mtxi,
                       const float* __restrict__ gridz)
{
    int t = threadIdx.x;               // 512 threads
    if (t < 256) {
        float s, c;
        sincospif((float)t / 256.0f, &s, &c);   // angle = pi*t/256 = 2*pi*t/512
        d_W512[t] = make_float2(c, -s);         // exp(-2*pi*i*t/512)
    }
    int mat = t >> 8;                  // 0 = mtx(+gridz^4), 1 = mtxi
    int m   = t & 255;
    const float* M = mat ? mtxi : mtx;
    int cnt = 0;
    for (int k = 0; k < 256; k++) {
        float v = M[m*256 + k];
        if (v != 0.0f) {
            float g = 1.0f;
            if (mat == 0) { float z = gridz[k]; float z2 = z*z; g = z2*z2; }
            d_cols[mat][m][cnt] = k;
            d_vals[mat][m][cnt] = v * g;
            cnt++;
        }
    }
    d_cnt[mat][m] = cnt;
}

// ---------------- resampling (sparse row apply) ----------------
// tmp[bd][m][hw] = sum_t mtx[m,t]*gz4[t]*feature[bd][t][hw]
__global__ __launch_bounds__(256) void k_resample_fwd(const float* __restrict__ feature)
{
    int hw = blockIdx.x*256 + threadIdx.x;
    int m  = blockIdx.y;
    int bd = blockIdx.z;
    int n  = d_cnt[0][m];
    const float* inb = feature + (size_t)bd*T_DIM*HW2;
    float acc = 0.f;
    for (int j = 0; j < n; j++)
        acc += d_vals[0][m][j] * inb[(size_t)d_cols[0][m][j]*HW2 + hw];
    d_tmp[((size_t)(bd*T_DIM + m))*HW2 + hw] = acc;
}

// out[bd][m][hw] = sum_t mtxi[m,t]*vol[bd][t][hw]   (vol lives in d_tmp)
__global__ __launch_bounds__(256) void k_resample_inv(float* __restrict__ out)
{
    int hw = blockIdx.x*256 + threadIdx.x;
    int m  = blockIdx.y;
    int bd = blockIdx.z;
    int n  = d_cnt[1][m];
    const float* inb = d_tmp + (size_t)bd*T_DIM*HW2;
    float acc = 0.f;
    for (int j = 0; j < n; j++)
        acc += d_vals[1][m][j] * inb[(size_t)d_cols[1][m][j]*HW2 + hw];
    out[((size_t)(bd*T_DIM + m))*HW2 + hw] = acc;
}

// ---------------- Pass A: W-axis forward R2C (128 real -> 256 FFT -> keep 129) ----------------
// 4 lines per block, 128 threads per line
__global__ __launch_bounds__(512) void k_fft_w_fwd()
{
    __shared__ float2 X[4][256];
    __shared__ float2 Wt[256];
    int tid = threadIdx.x;
    if (tid < 256) Wt[tid] = d_W512[tid];
    int line = tid >> 7, j = tid & 127;
    size_t L = (size_t)blockIdx.x*4 + line;      // (bd*256+m)*128 + h
    const float* in = d_tmp + L*HW;
    X[line][brev8(j)]       = make_float2(in[j], 0.f);
    X[line][brev8(j + 128)] = make_float2(0.f, 0.f);
    __syncthreads();
    for (int half = 1; half < 256; half <<= 1) {
        int r   = j & (half-1);
        int pos = ((j & ~(half-1)) << 1) | r;
        float2 w = Wt[r * (256/half)];
        float2 a = X[line][pos], b = X[line][pos+half];
        float2 t = cmul(b, w);
        X[line][pos]      = cadd(a, t);
        X[line][pos+half] = csub(a, t);
        __syncthreads();
    }
    float2* out = d_bufA + L*KWS;
    out[j] = X[line][j];
    if (j == 0) out[128] = X[line][128];
}

// ---------------- Pass B: H-axis forward (128 -> 256, zero-padded), per (bd,m,kw-tile16) ----------------
__global__ __launch_bounds__(512) void k_fft_h_fwd()
{
    __shared__ float2 X[256][16];
    __shared__ float2 Wt[256];
    int tid = threadIdx.x;
    if (tid < 256) Wt[tid] = d_W512[tid];
    int kw0 = blockIdx.x * 16;
    int m   = blockIdx.y;
    int bd  = blockIdx.z;
    const float2* in = d_bufA + ((size_t)(bd*T_DIM + m))*HW*KWS;
    for (int idx = tid; idx < 256*16; idx += 512) {
        int h = idx >> 4, kwl = idx & 15, kw = kw0 + kwl;
        float2 v = make_float2(0.f, 0.f);
        if (h < 128 && kw < KW) v = in[h*KWS + kw];
        X[brev8(h)][kwl] = v;
    }
    __syncthreads();
    for (int half = 1; half < 256; half <<= 1) {
        #pragma unroll
        for (int q = 0; q < 4; q++) {
            int b   = tid + q*512;
            int kwl = b & 15, j = b >> 4;
            int r   = j & (half-1);
            int pos = ((j & ~(half-1)) << 1) | r;
            float2 w  = Wt[r * (256/half)];
            float2 a  = X[pos][kwl], bb = X[pos+half][kwl];
            float2 t  = cmul(bb, w);
            X[pos][kwl]      = cadd(a, t);
            X[pos+half][kwl] = csub(a, t);
        }
        __syncthreads();
    }
    float2* out = d_bufB + ((size_t)(bd*T_DIM + m))*T_DIM*KWS;
    for (int idx = tid; idx < 256*16; idx += 512) {
        int kh = idx >> 4, kwl = idx & 15, kw = kw0 + kwl;
        if (kw < KW) out[kh*KWS + kw] = X[kh][kwl];
    }
}

// ---------------- Pass C: T-axis fwd(256->512, padded) * invpsf * inv, crop t<256, in-place ----------------
__global__ __launch_bounds__(512) void k_fft_t(const float* __restrict__ pr, const float* __restrict__ pi)
{
    __shared__ float2 X[512][8];
    __shared__ float2 Wt[256];
    int tid = threadIdx.x;
    if (tid < 256) Wt[tid] = d_W512[tid];
    int kw0 = blockIdx.x * 8;
    int kh  = blockIdx.y;
    int bd  = blockIdx.z;
    float2* base = d_bufB + (size_t)bd*T_DIM*T_DIM*KWS + (size_t)kh*KWS;
    const int TSTR = T_DIM*KWS;
    for (int idx = tid; idx < 512*8; idx += 512) {
        int t = idx >> 3, kwl = idx & 7, kw = kw0 + kwl;
        float2 v = make_float2(0.f, 0.f);
        if (t < 256 && kw < KW) v = base[(size_t)t*TSTR + kw];
        X[brev9(t)][kwl] = v;
    }
    __syncthreads();
    // forward DIT (9 stages)
    for (int half = 1; half < 512; half <<= 1) {
        #pragma unroll
        for (int q = 0; q < 4; q++) {
            int b   = tid + q*512;               // 2048 butterflies
            int kwl = b & 7, j = b >> 3;         // j in [0,256)
            int r   = j & (half-1);
            int pos = ((j & ~(half-1)) << 1) | r;
            float2 w  = Wt[r * (256/half)];
            float2 a  = X[pos][kwl], bb = X[pos+half][kwl];
            float2 t2 = cmul(bb, w);
            X[pos][kwl]      = cadd(a, t2);
            X[pos+half][kwl] = csub(a, t2);
        }
        __syncthreads();
    }
    // pointwise Wiener filter multiply (fold the full ifftn normalization here)
    const float NORM = 1.0f / 33554432.0f;       // 1/(512*256*256)
    for (int idx = tid; idx < 512*8; idx += 512) {
        int kt = idx >> 3, kwl = idx & 7, kw = kw0 + kwl;
        if (kw < KW) {
            size_t o = ((size_t)kt*256 + kh)*256 + kw;
            float2 p = make_float2(pr[o]*NORM, pi[o]*NORM);
            X[kt][kwl] = cmul(X[kt][kwl], p);
        }
    }
    __syncthreads();
    // inverse DIF (conj twiddles), output bit-reversed
    for (int half = 256; half >= 1; half >>= 1) {
        #pragma unroll
        for (int q = 0; q < 4; q++) {
            int b   = tid + q*512;
            int kwl = b & 7, j = b >> 3;
            int r   = j & (half-1);
            int pos = ((j & ~(half-1)) << 1) | r;
            float2 w = Wt[r * (256/half)]; w.y = -w.y;
            float2 a = X[pos][kwl], bb = X[pos+half][kwl];
            X[pos][kwl]      = cadd(a, bb);
            X[pos+half][kwl] = cmul(csub(a, bb), w);
        }
        __syncthreads();
    }
    // write cropped t<256 (undo bit reversal on read)
    for (int idx = tid; idx < 256*8; idx += 512) {
        int t = idx >> 3, kwl = idx & 7, kw = kw0 + kwl;
        if (kw < KW) base[(size_t)t*TSTR + kw] = X[brev9(t)][kwl];
    }
}

// ---------------- Pass D: H-axis inverse (256 -> crop 128), per (bd,t,kw-tile16) ----------------
__global__ __launch_bounds__(512) void k_fft_h_inv()
{
    __shared__ float2 X[256][16];
    __shared__ float2 Wt[256];
    int tid = threadIdx.x;
    if (tid < 256) Wt[tid] = d_W512[tid];
    int kw0 = blockIdx.x * 16;
    int t   = blockIdx.y;
    int bd  = blockIdx.z;
    const float2* in = d_bufB + ((size_t)(bd*T_DIM + t))*T_DIM*KWS;
    for (int idx = tid; idx < 256*16; idx += 512) {
        int kh = idx >> 4, kwl = idx & 15, kw = kw0 + kwl;
        float2 v = make_float2(0.f, 0.f);
        if (kw < KW) v = in[kh*KWS + kw];
        X[brev8(kh)][kwl] = v;
    }
    __syncthreads();
    for (int half = 1; half < 256; half <<= 1) {
        #pragma unroll
        for (int q = 0; q < 4; q++) {
            int b   = tid + q*512;
            int kwl = b & 15, j = b >> 4;
            int r   = j & (half-1);
            int pos = ((j & ~(half-1)) << 1) | r;
            float2 w = Wt[r * (256/half)]; w.y = -w.y;   // conj for inverse
            float2 a = X[pos][kwl], bb = X[pos+half][kwl];
            float2 t2 = cmul(bb, w);
            X[pos][kwl]      = cadd(a, t2);
            X[pos+half][kwl] = csub(a, t2);
        }
        __syncthreads();
    }
    float2* out = d_bufA + ((size_t)(bd*T_DIM + t))*HW*KWS;
    for (int idx = tid; idx < 128*16; idx += 512) {
        int h = idx >> 4, kwl = idx & 15, kw = kw0 + kwl;
        if (kw < KW) out[h*KWS + kw] = X[h][kwl];
    }
}

// ---------------- Pass E: W-axis inverse C2R (Hermitian 129 -> 256 -> real crop 128) ----------------
__global__ __launch_bounds__(512) void k_fft_w_inv()
{
    __shared__ float2 X[4][256];
    __shared__ float2 Wt[256];
    int tid = threadIdx.x;
    if (tid < 256) Wt[tid] = d_W512[tid];
    int line = tid >> 7, j = tid & 127;
    size_t L = (size_t)blockIdx.x*4 + line;      // (bd*256+t)*128 + h
    const float2* in = d_bufA + L*KWS;
    float2 v0 = in[j];
    float2 v1;
    if (j == 0) v1 = in[128];
    else { float2 c = in[128 - j]; v1 = make_float2(c.x, -c.y); }   // conj(in[256-(j+128)])
    X[line][brev8(j)]       = v0;
    X[line][brev8(j + 128)] = v1;
    __syncthreads();
    for (int half = 1; half < 256; half <<= 1) {
        int r   = j & (half-1);
        int pos = ((j & ~(half-1)) << 1) | r;
        float2 w = Wt[r * (256/half)]; w.y = -w.y;   // conj for inverse
        float2 a = X[line][pos], b = X[line][pos+half];
        float2 t = cmul(b, w);
        X[line][pos]      = cadd(a, t);
        X[line][pos+half] = csub(a, t);
        __syncthreads();
    }
    d_tmp[L*HW + j] = X[line][j].x;   // real part, crop w<128
}

// ---------------- launch ----------------
extern "C" void kernel_launch(void* const* d_in, const int* in_sizes, int n_in,
                              void* d_out, int out_size)
{
    (void)in_sizes; (void)n_in; (void)out_size;
    const float* feature = (const float*)d_in[0];
    const float* gridz   = (const float*)d_in[1];
    const float* mtx     = (const float*)d_in[2];
    const float* mtxi    = (const float*)d_in[3];
    const float* pr      = (const float*)d_in[4];
    const float* pi      = (const float*)d_in[5];
    float* out = (float*)d_out;

    k_init<<<1, 512>>>(mtx, mtxi, gridz);

    k_resample_fwd<<<dim3(HW2/256, 256, BD), 256>>>(feature);

    k_fft_w_fwd<<<(BD*T_DIM*HW)/4, 512>>>();                 // 16384 blocks

    k_fft_h_fwd<<<dim3((KW + 15)/16, T_DIM, BD), 512>>>();   // 9 x 256 x 2

    k_fft_t<<<dim3((KW + 7)/8, T_DIM, BD), 512>>>(pr, pi);   // 17 x 256 x 2

    k_fft_h_inv<<<dim3((KW + 15)/16, T_DIM, BD), 512>>>();

    k_fft_w_inv<<<(BD*T_DIM*HW)/4, 512>>>();

    k_resample_inv<<<dim3(HW2/256, 256, BD), 256>>>(out);
}

// round 2
// speedup vs baseline: 1.3790x; 1.3790x over previous
#include <cuda_runtime.h>
#include <cstdint>

// ---------------- problem dims ----------------
#define T_DIM 256      // temporal crop
#define HW    128      // spatial H == W
#define HW2   (HW*HW)  // 16384
#define KW    129      // half-spectrum bins along W (Hermitian)
#define KWS   132      // padded stride for kw rows (float2)
#define BD    2        // b*d

// ---------------- device scratch (no allocation allowed) ----------------
__device__ static float  d_tmp [(size_t)BD*T_DIM*HW*HW];
__device__ static float2 d_bufA[(size_t)BD*T_DIM*HW*KWS];
__device__ static float2 d_bufB[(size_t)BD*T_DIM*T_DIM*KWS];
__device__ static float2 d_W512[256];                       // exp(-i*pi*k/256)
__device__ static int    d_cols[2][256][256];
__device__ static float  d_vals[2][256][256];
__device__ static int    d_cnt [2][256];

// ---------------- complex helpers ----------------
static __device__ __forceinline__ float2 cadd(float2 a, float2 b){ return make_float2(a.x+b.x, a.y+b.y); }
static __device__ __forceinline__ float2 csub(float2 a, float2 b){ return make_float2(a.x-b.x, a.y-b.y); }
static __device__ __forceinline__ float2 cmul(float2 a, float2 b){ return make_float2(a.x*b.x - a.y*b.y, a.x*b.y + a.y*b.x); }
static __device__ __forceinline__ float2 rot_mi(float2 a){ return make_float2(a.y, -a.x); }   // * (-i)
static __device__ __forceinline__ float2 rot_pi(float2 a){ return make_float2(-a.y, a.x); }   // * (+i)

static __device__ __forceinline__ int brev8(int i){ return __brev((unsigned)i) >> 24; }
static __device__ __forceinline__ int brev9(int i){ return __brev((unsigned)i) >> 23; }

// ---------------- init: twiddle table + CSR of mtx/mtxi ----------------
__global__ void k_init(const float* __restrict__ mtx, const float* __restrict__ mtxi,
                       const float* __restrict__ gridz)
{
    int t = threadIdx.x;               // 512 threads
    if (t < 256) {
        float s, c;
        sincospif((float)t / 256.0f, &s, &c);
        d_W512[t] = make_float2(c, -s);
    }
    int mat = t >> 8;
    int m   = t & 255;
    const float* M = mat ? mtxi : mtx;
    int cnt = 0;
    for (int k = 0; k < 256; k++) {
        float v = M[m*256 + k];
        if (v != 0.0f) {
            float g = 1.0f;
            if (mat == 0) { float z = gridz[k]; float z2 = z*z; g = z2*z2; }
            d_cols[mat][m][cnt] = k;
            d_vals[mat][m][cnt] = v * g;
            cnt++;
        }
    }
    d_cnt[mat][m] = cnt;
}

// ---------------- resampling (sparse row apply) ----------------
__global__ __launch_bounds__(256) void k_resample_fwd(const float* __restrict__ feature)
{
    int hw = blockIdx.x*256 + threadIdx.x;
    int m  = blockIdx.y;
    int bd = blockIdx.z;
    int n  = d_cnt[0][m];
    const float* inb = feature + (size_t)bd*T_DIM*HW2;
    float acc = 0.f;
    for (int j = 0; j < n; j++)
        acc += d_vals[0][m][j] * inb[(size_t)d_cols[0][m][j]*HW2 + hw];
    d_tmp[((size_t)(bd*T_DIM + m))*HW2 + hw] = acc;
}

__global__ __launch_bounds__(256) void k_resample_inv(float* __restrict__ out)
{
    int hw = blockIdx.x*256 + threadIdx.x;
    int m  = blockIdx.y;
    int bd = blockIdx.z;
    int n  = d_cnt[1][m];
    const float* inb = d_tmp + (size_t)bd*T_DIM*HW2;
    float acc = 0.f;
    for (int j = 0; j < n; j++)
        acc += d_vals[1][m][j] * inb[(size_t)d_cols[1][m][j]*HW2 + hw];
    out[((size_t)(bd*T_DIM + m))*HW2 + hw] = acc;
}

// ============ Pass A: W-axis forward R2C (128 real -> 256 FFT -> keep 129) ============
// 8 lines/block, layout X[pos][line] with pad. 512 threads: line = tid&7, q = tid>>3 (64)
__global__ __launch_bounds__(512) void k_fft_w_fwd()
{
    __shared__ float2 X[256][9];
    __shared__ float2 Wt[256];
    int tid = threadIdx.x;
    if (tid < 256) Wt[tid] = d_W512[tid];
    int ln = tid & 7, q = tid >> 3;                 // q in [0,64)
    size_t L = (size_t)blockIdx.x*8 + ln;           // (bd*256+m)*128 + h
    const float* in = d_tmp + L*HW;
    #pragma unroll
    for (int k = 0; k < 2; k++) {                   // duplicate-fill (skips padded stage 1)
        int h = q + 64*k;
        float v = in[h];
        int p = brev8(h);
        X[p][ln] = make_float2(v, 0.f);
        X[p+1][ln] = make_float2(v, 0.f);
    }
    __syncthreads();
    #pragma unroll
    for (int hi = 0; hi < 3; hi++) {                // radix-4 at h = 2, 8, 32
        const int h = 2 << (2*hi);
        int r = q & (h-1);
        int base = ((q & ~(h-1)) << 2) | r;
        float2 w1 = Wt[r*(256/h)];
        float2 w2 = Wt[r*(128/h)];
        float2 a0 = X[base][ln], a1 = X[base+h][ln], a2 = X[base+2*h][ln], a3 = X[base+3*h][ln];
        float2 t1 = cmul(a1, w1), t3 = cmul(a3, w1);
        float2 b0 = cadd(a0,t1), b1 = csub(a0,t1);
        float2 b2 = cadd(a2,t3), b3 = csub(a2,t3);
        float2 u2 = cmul(b2, w2), u3 = rot_mi(cmul(b3, w2));
        X[base][ln]     = cadd(b0,u2);
        X[base+2*h][ln] = csub(b0,u2);
        X[base+h][ln]   = cadd(b1,u3);
        X[base+3*h][ln] = csub(b1,u3);
        __syncthreads();
    }
    #pragma unroll
    for (int k = 0; k < 2; k++) {                   // radix-2 at h = 128
        int j = q + 64*k;
        float2 w = Wt[2*j];
        float2 a = X[j][ln], c = cmul(X[j+128][ln], w);
        X[j][ln] = cadd(a,c); X[j+128][ln] = csub(a,c);
    }
    __syncthreads();
    float2* out = d_bufA + L*KWS;
    out[q] = X[q][ln];
    out[q+64] = X[q+64][ln];
    if (q == 0) out[128] = X[128][ln];
}

// ============ Pass B: H-axis forward (128 -> 256, zero-padded), per (bd,m,kw-tile16) ============
__global__ __launch_bounds__(512) void k_fft_h_fwd()
{
    __shared__ float2 X[256][17];
    __shared__ float2 Wt[256];
    int tid = threadIdx.x;
    if (tid < 256) Wt[tid] = d_W512[tid];
    int kw0 = blockIdx.x * 16;
    const float2* in = d_bufA + ((size_t)(blockIdx.z*T_DIM + blockIdx.y))*HW*KWS;
    #pragma unroll
    for (int it = 0; it < 4; it++) {                // duplicate-fill of 128 real rows
        int idx = tid + it*512;
        int h = idx >> 4, kwl = idx & 15, kw = kw0 + kwl;
        float2 v = make_float2(0.f, 0.f);
        if (kw < KW) v = in[h*KWS + kw];
        int p = brev8(h);
        X[p][kwl] = v; X[p+1][kwl] = v;
    }
    __syncthreads();
    #pragma unroll
    for (int hi = 0; hi < 3; hi++) {                // radix-4 at h = 2, 8, 32
        const int h = 2 << (2*hi);
        #pragma unroll
        for (int it = 0; it < 2; it++) {
            int b = tid + it*512;
            int kwl = b & 15, q = b >> 4;           // q in [0,64)
            int r = q & (h-1);
            int base = ((q & ~(h-1)) << 2) | r;
            float2 w1 = Wt[r*(256/h)];
            float2 w2 = Wt[r*(128/h)];
            float2 a0 = X[base][kwl], a1 = X[base+h][kwl], a2 = X[base+2*h][kwl], a3 = X[base+3*h][kwl];
            float2 t1 = cmul(a1, w1), t3 = cmul(a3, w1);
            float2 b0 = cadd(a0,t1), b1 = csub(a0,t1);
            float2 b2 = cadd(a2,t3), b3 = csub(a2,t3);
            float2 u2 = cmul(b2, w2), u3 = rot_mi(cmul(b3, w2));
            X[base][kwl]     = cadd(b0,u2);
            X[base+2*h][kwl] = csub(b0,u2);
            X[base+h][kwl]   = cadd(b1,u3);
            X[base+3*h][kwl] = csub(b1,u3);
        }
        __syncthreads();
    }
    #pragma unroll
    for (int it = 0; it < 4; it++) {                // radix-2 at h = 128
        int b = tid + it*512;
        int kwl = b & 15, j = b >> 4;               // j in [0,128)
        float2 w = Wt[2*j];
        float2 a = X[j][kwl], c = cmul(X[j+128][kwl], w);
        X[j][kwl] = cadd(a,c); X[j+128][kwl] = csub(a,c);
    }
    __syncthreads();
    float2* out = d_bufB + ((size_t)(blockIdx.z*T_DIM + blockIdx.y))*T_DIM*KWS;
    #pragma unroll
    for (int it = 0; it < 8; it++) {
        int idx = tid + it*512;
        int kh = idx >> 4, kwl = idx & 15, kw = kw0 + kwl;
        if (kw < KW) out[kh*KWS + kw] = X[kh][kwl];
    }
}

// ============ Pass C: T-axis fwd(256->512) * invpsf * inv, crop t<256, in-place ============
__global__ __launch_bounds__(512) void k_fft_t(const float* __restrict__ pr, const float* __restrict__ pi)
{
    __shared__ float2 X[512][9];
    __shared__ float2 Wt[256];
    int tid = threadIdx.x;
    if (tid < 256) Wt[tid] = d_W512[tid];
    int kw0 = blockIdx.x * 8;
    int kh  = blockIdx.y;
    int bd  = blockIdx.z;
    float2* base_p = d_bufB + (size_t)bd*T_DIM*T_DIM*KWS + (size_t)kh*KWS;
    const int TSTR = T_DIM*KWS;
    #pragma unroll
    for (int it = 0; it < 4; it++) {                // duplicate-fill 256 real t-rows
        int idx = tid + it*512;
        int t = idx >> 3, kwl = idx & 7, kw = kw0 + kwl;
        float2 v = make_float2(0.f, 0.f);
        if (kw < KW) v = base_p[(size_t)t*TSTR + kw];
        int p = brev9(t);
        X[p][kwl] = v; X[p+1][kwl] = v;
    }
    __syncthreads();
    #pragma unroll
    for (int hi = 0; hi < 4; hi++) {                // forward radix-4 at h = 2, 8, 32, 128
        const int h = 2 << (2*hi);
        #pragma unroll
        for (int it = 0; it < 2; it++) {
            int b = tid + it*512;
            int kwl = b & 7, q = b >> 3;            // q in [0,128)
            int r = q & (h-1);
            int bs = ((q & ~(h-1)) << 2) | r;
            float2 w1 = Wt[r*(256/h)];
            float2 w2 = Wt[r*(128/h)];
            float2 a0 = X[bs][kwl], a1 = X[bs+h][kwl], a2 = X[bs+2*h][kwl], a3 = X[bs+3*h][kwl];
            float2 t1 = cmul(a1, w1), t3 = cmul(a3, w1);
            float2 b0 = cadd(a0,t1), b1 = csub(a0,t1);
            float2 b2 = cadd(a2,t3), b3 = csub(a2,t3);
            float2 u2 = cmul(b2, w2), u3 = rot_mi(cmul(b3, w2));
            X[bs][kwl]     = cadd(b0,u2);
            X[bs+2*h][kwl] = csub(b0,u2);
            X[bs+h][kwl]   = cadd(b1,u3);
            X[bs+3*h][kwl] = csub(b1,u3);
        }
        __syncthreads();
    }
    // pointwise Wiener filter multiply (ifftn normalization folded in)
    const float NORM = 1.0f / 33554432.0f;
    #pragma unroll
    for (int it = 0; it < 8; it++) {
        int idx = tid + it*512;
        int kt = idx >> 3, kwl = idx & 7, kw = kw0 + kwl;
        if (kw < KW) {
            size_t o = ((size_t)kt*256 + kh)*256 + kw;
            float2 p = make_float2(pr[o]*NORM, pi[o]*NORM);
            X[kt][kwl] = cmul(X[kt][kwl], p);
        }
    }
    __syncthreads();
    #pragma unroll
    for (int hi = 0; hi < 4; hi++) {                // inverse DIF radix-4: H = 256, 64, 16, 4
        const int H = 256 >> (2*hi);
        const int Hh = H >> 1;
        #pragma unroll
        for (int it = 0; it < 2; it++) {
            int b = tid + it*512;
            int kwl = b & 7, q = b >> 3;            // q in [0,128)
            int r = q & (Hh-1);
            int bs = ((q & ~(Hh-1)) << 2) | r;
            float2 w1 = Wt[r*(256/H)];  w1.y = -w1.y;
            float2 wh = Wt[r*(512/H)];  wh.y = -wh.y;
            float2 e0 = X[bs][kwl], e1 = X[bs+Hh][kwl], e2 = X[bs+H][kwl], e3 = X[bs+H+Hh][kwl];
            float2 b0 = cadd(e0,e2);
            float2 b2 = cmul(csub(e0,e2), w1);
            float2 b1 = cadd(e1,e3);
            float2 b3 = rot_pi(cmul(csub(e1,e3), w1));
            X[bs][kwl]      = cadd(b0,b1);
            X[bs+Hh][kwl]   = cmul(csub(b0,b1), wh);
            X[bs+H][kwl]    = cadd(b2,b3);
            X[bs+H+Hh][kwl] = cmul(csub(b2,b3), wh);
        }
        __syncthreads();
    }
    #pragma unroll
    for (int it = 0; it < 4; it++) {                // final inverse radix-2, half = 1 (w = 1)
        int b = tid + it*512;
        int kwl = b & 7, j = b >> 3;                // j in [0,256)
        float2 a = X[2*j][kwl], c = X[2*j+1][kwl];
        X[2*j][kwl] = cadd(a,c); X[2*j+1][kwl] = csub(a,c);
    }
    __syncthreads();
    #pragma unroll
    for (int it = 0; it < 4; it++) {                // crop t<256, undo bit reversal
        int idx = tid + it*512;
        int t = idx >> 3, kwl = idx & 7, kw = kw0 + kwl;
        if (kw < KW) base_p[(size_t)t*TSTR + kw] = X[brev9(t)][kwl];
    }
}

// ============ Pass D: H-axis inverse (256 -> crop 128), per (bd,t,kw-tile16) ============
__global__ __launch_bounds__(512) void k_fft_h_inv()
{
    __shared__ float2 X[256][17];
    __shared__ float2 Wt[256];
    int tid = threadIdx.x;
    if (tid < 256) Wt[tid] = d_W512[tid];
    int kw0 = blockIdx.x * 16;
    const float2* in = d_bufB + ((size_t)(blockIdx.z*T_DIM + blockIdx.y))*T_DIM*KWS;
    #pragma unroll
    for (int it = 0; it < 8; it++) {
        int idx = tid + it*512;
        int kh = idx >> 4, kwl = idx & 15, kw = kw0 + kwl;
        float2 v = make_float2(0.f, 0.f);
        if (kw < KW) v = in[kh*KWS + kw];
        X[brev8(kh)][kwl] = v;
    }
    __syncthreads();
    #pragma unroll
    for (int hi = 0; hi < 4; hi++) {                // inverse radix-4 at h = 1, 4, 16, 64
        const int h = 1 << (2*hi);
        #pragma unroll
        for (int it = 0; it < 2; it++) {
            int b = tid + it*512;
            int kwl = b & 15, q = b >> 4;           // q in [0,64)
            int r = q & (h-1);
            int bs = ((q & ~(h-1)) << 2) | r;
            float2 w1 = Wt[r*(256/h)];  w1.y = -w1.y;
            float2 w2 = Wt[r*(128/h)];  w2.y = -w2.y;
            float2 a0 = X[bs][kwl], a1 = X[bs+h][kwl], a2 = X[bs+2*h][kwl], a3 = X[bs+3*h][kwl];
            float2 t1 = cmul(a1, w1), t3 = cmul(a3, w1);
            float2 b0 = cadd(a0,t1), b1 = csub(a0,t1);
            float2 b2 = cadd(a2,t3), b3 = csub(a2,t3);
            float2 u2 = cmul(b2, w2), u3 = rot_pi(cmul(b3, w2));
            X[bs][kwl]     = cadd(b0,u2);
            X[bs+2*h][kwl] = csub(b0,u2);
            X[bs+h][kwl]   = cadd(b1,u3);
            X[bs+3*h][kwl] = csub(b1,u3);
        }
        __syncthreads();
    }
    float2* out = d_bufA + ((size_t)(blockIdx.z*T_DIM + blockIdx.y))*HW*KWS;
    #pragma unroll
    for (int it = 0; it < 4; it++) {                // crop h < 128
        int idx = tid + it*512;
        int h = idx >> 4, kwl = idx & 15, kw = kw0 + kwl;
        if (kw < KW) out[h*KWS + kw] = X[h][kwl];
    }
}

// ============ Pass E: W-axis inverse C2R (Hermitian 129 -> 256 -> real crop 128) ============
__global__ __launch_bounds__(512) void k_fft_w_inv()
{
    __shared__ float2 X[256][9];
    __shared__ float2 Wt[256];
    int tid = threadIdx.x;
    if (tid < 256) Wt[tid] = d_W512[tid];
    int ln = tid & 7, q = tid >> 3;                 // q in [0,64)
    size_t L = (size_t)blockIdx.x*8 + ln;           // (bd*256+t)*128 + h
    const float2* in = d_bufA + L*KWS;
    #pragma unroll
    for (int k = 0; k < 4; k++) {
        int e = q + 64*k;
        float2 v;
        if (e <= 128) v = in[e];
        else { float2 c = in[256-e]; v = make_float2(c.x, -c.y); }
        X[brev8(e)][ln] = v;
    }
    __syncthreads();
    #pragma unroll
    for (int hi = 0; hi < 4; hi++) {                // inverse radix-4 at h = 1, 4, 16, 64
        const int h = 1 << (2*hi);
        int r = q & (h-1);
        int bs = ((q & ~(h-1)) << 2) | r;
        float2 w1 = Wt[r*(256/h)];  w1.y = -w1.y;
        float2 w2 = Wt[r*(128/h)];  w2.y = -w2.y;
        float2 a0 = X[bs][ln], a1 = X[bs+h][ln], a2 = X[bs+2*h][ln], a3 = X[bs+3*h][ln];
        float2 t1 = cmul(a1, w1), t3 = cmul(a3, w1);
        float2 b0 = cadd(a0,t1), b1 = csub(a0,t1);
        float2 b2 = cadd(a2,t3), b3 = csub(a2,t3);
        float2 u2 = cmul(b2, w2), u3 = rot_pi(cmul(b3, w2));
        X[bs][ln]     = cadd(b0,u2);
        X[bs+2*h][ln] = csub(b0,u2);
        X[bs+h][ln]   = cadd(b1,u3);
        X[bs+3*h][ln] = csub(b1,u3);
        __syncthreads();
    }
    float* out = d_tmp + L*HW;
    out[q]      = X[q][ln].x;
    out[q + 64] = X[q + 64][ln].x;
}

// ---------------- launch ----------------
extern "C" void kernel_launch(void* const* d_in, const int* in_sizes, int n_in,
                              void* d_out, int out_size)
{
    (void)in_sizes; (void)n_in; (void)out_size;
    const float* feature = (const float*)d_in[0];
    const float* gridz   = (const float*)d_in[1];
    const float* mtx     = (const float*)d_in[2];
    const float* mtxi    = (const float*)d_in[3];
    const float* pr      = (const float*)d_in[4];
    const float* pi      = (const float*)d_in[5];
    float* out = (float*)d_out;

    k_init<<<1, 512>>>(mtx, mtxi, gridz);

    k_resample_fwd<<<dim3(HW2/256, 256, BD), 256>>>(feature);

    k_fft_w_fwd<<<(BD*T_DIM*HW)/8, 512>>>();                 // 8192 blocks

    k_fft_h_fwd<<<dim3((KW + 15)/16, T_DIM, BD), 512>>>();   // 9 x 256 x 2

    k_fft_t<<<dim3((KW + 7)/8, T_DIM, BD), 512>>>(pr, pi);   // 17 x 256 x 2

    k_fft_h_inv<<<dim3((KW + 15)/16, T_DIM, BD), 512>>>();

    k_fft_w_inv<<<(BD*T_DIM*HW)/8, 512>>>();

    k_resample_inv<<<dim3(HW2/256, 256, BD), 256>>>(out);
}